// round 4
// baseline (speedup 1.0000x reference)
#include <cuda_runtime.h>
#include <cuda_bf16.h>
#include <math.h>
#include <stdint.h>

#define N_ENTS  100000
#define N_RELS  64
#define EDIM    128
#define KNBR    32
#define BATCH   16384

// ---------------- device-global scratch ------------------------------------------
__device__ float g_EntN[(size_t)N_ENTS * EDIM];
__device__ float g_TrT [(size_t)N_ENTS * EDIM];
__device__ float g_RelN[(size_t)N_RELS * EDIM];
__device__ float g_X1  [(size_t)BATCH * EDIM];
__device__ float g_X2  [(size_t)BATCH * EDIM];

// ---------------- helpers ----------------------------------------------------------
__device__ __forceinline__ uint32_t smem_u32(const void* p) {
    uint32_t a;
    asm("{ .reg .u64 t; cvta.to.shared.u64 t, %1; cvt.u32.u64 %0, t; }" : "=r"(a) : "l"(p));
    return a;
}
__device__ __forceinline__ void ldmx4(uint32_t& r0, uint32_t& r1, uint32_t& r2, uint32_t& r3,
                                      uint32_t addr) {
    asm volatile("ldmatrix.sync.aligned.m8n8.x4.shared.b16 {%0,%1,%2,%3}, [%4];"
                 : "=r"(r0), "=r"(r1), "=r"(r2), "=r"(r3) : "r"(addr));
}
__device__ __forceinline__ void mma_bf16(float* d, const uint32_t* a, const uint32_t* b) {
    asm volatile(
        "mma.sync.aligned.m16n8k16.row.col.f32.bf16.bf16.f32 "
        "{%0,%1,%2,%3}, {%4,%5,%6,%7}, {%8,%9}, {%0,%1,%2,%3};"
        : "+f"(d[0]), "+f"(d[1]), "+f"(d[2]), "+f"(d[3])
        : "r"(a[0]), "r"(a[1]), "r"(a[2]), "r"(a[3]), "r"(b[0]), "r"(b[1]));
}
__device__ __forceinline__ uint32_t pk_bf2(__nv_bfloat16 a, __nv_bfloat16 b) {
    __nv_bfloat162 t(a, b);
    return *(uint32_t*)&t;
}

// padded bf16 tiles, row stride 136 elems (272 B) -> conflict-free ldmatrix
#define LDT 136
#define A_TILE_B (64  * LDT * 2)   // 17408
#define B_TILE_B (128 * LDT * 2)   // 34816
#define OFF_BIAS 0
#define OFF_AH   512
#define OFF_AL   (512 + A_TILE_B)                 // 17920
#define OFF_BH   (512 + 2 * A_TILE_B)             // 35328
#define OFF_BL   (512 + 2 * A_TILE_B + B_TILE_B)  // 70144
#define SMEM_MM  (512 + 2 * A_TILE_B + 2 * B_TILE_B)  // 104960 B -> 2 CTAs/SM

// split an fp32 tile (rows_total rows of 128) into bf16 hi/lo, store padded smem
template <int ROWS>
__device__ __forceinline__ void load_split(const float* __restrict__ src, int rows_valid,
                                           char* sm, int off_h, int off_l, int tid) {
    #pragma unroll
    for (int i = 0; i < ROWS * 16 / 256; i++) {
        int g = tid + i * 256;
        int row = g >> 4, c8 = g & 15, col0 = c8 * 8;
        float4 v0 = make_float4(0.f, 0.f, 0.f, 0.f), v1 = v0;
        if (row < rows_valid) {
            const float4* p = (const float4*)src + (size_t)row * 32 + c8 * 2;
            v0 = p[0];
            v1 = p[1];
        }
        float f[8] = {v0.x, v0.y, v0.z, v0.w, v1.x, v1.y, v1.z, v1.w};
        __nv_bfloat16 h[8], l[8];
        #pragma unroll
        for (int j = 0; j < 8; j++) {
            h[j] = __float2bfloat16(f[j]);
            l[j] = __float2bfloat16(f[j] - __bfloat162float(h[j]));
        }
        uint4 hv = make_uint4(pk_bf2(h[0], h[1]), pk_bf2(h[2], h[3]),
                              pk_bf2(h[4], h[5]), pk_bf2(h[6], h[7]));
        uint4 lv = make_uint4(pk_bf2(l[0], l[1]), pk_bf2(l[2], l[3]),
                              pk_bf2(l[4], l[5]), pk_bf2(l[6], l[7]));
        size_t o = (size_t)row * LDT * 2 + col0 * 2;
        *(uint4*)(sm + off_h + o) = hv;
        *(uint4*)(sm + off_l + o) = lv;
    }
}

// ---------------- mma.sync GEMM: C[M,128] = epi(A[M,128] @ B[128,128]^T + bias) ----
// CTA tile 64x128, 256 threads (2x4 warp grid, 32x32 warp tiles), 2 CTAs/SM.
// MODE 0: store; MODE 1: store leaky; MODE 2: += leaky
template <int MODE>
__global__ __launch_bounds__(256, 2) void k_gemm_mma(const float* __restrict__ A,
                                                     const float* __restrict__ B,
                                                     const float* __restrict__ bias,
                                                     float* __restrict__ C, int M) {
    extern __shared__ char sm[];
    uint32_t smb = smem_u32(sm);
    int tid  = threadIdx.x;
    int wid  = tid >> 5, lane = tid & 31;
    int wy   = wid >> 2, wx = wid & 3;          // 2 x 4 warp grid
    int m0   = blockIdx.x * 64;

    if (tid < 128) ((float*)(sm + OFF_BIAS))[tid] = bias[tid];
    load_split<64>(A + (size_t)m0 * EDIM, M - m0, sm, OFF_AH, OFF_AL, tid);
    load_split<128>(B, 128, sm, OFF_BH, OFF_BL, tid);
    __syncthreads();

    // per-lane ldmatrix base offsets
    int rowA  = wy * 32 + (lane & 15);                        // + mi*16
    int colA  = (lane >> 4) * 8;                              // + k0
    int nrow  = wx * 32 + (lane & 7) + ((lane >> 4) ? 8 : 0); // + nj2*16
    int kaddB = ((lane >> 3) & 1) * 8;                        // + k0

    uint32_t aBaseH = smb + OFF_AH, aBaseL = smb + OFF_AL;
    uint32_t bBaseH = smb + OFF_BH, bBaseL = smb + OFF_BL;

    float d[2][4][4];
    #pragma unroll
    for (int i = 0; i < 2; i++)
        #pragma unroll
        for (int j = 0; j < 4; j++)
            #pragma unroll
            for (int q = 0; q < 4; q++) d[i][j][q] = 0.f;

    #pragma unroll
    for (int pass = 0; pass < 3; pass++) {
        uint32_t aB = (pass == 2) ? aBaseL : aBaseH;
        uint32_t bB = (pass == 1) ? bBaseL : bBaseH;
        #pragma unroll
        for (int ks = 0; ks < 8; ks++) {
            int k0 = ks * 16;
            uint32_t a[2][4];
            #pragma unroll
            for (int mi = 0; mi < 2; mi++) {
                uint32_t addr = aB + (uint32_t)(((rowA + mi * 16) * LDT + k0 + colA) * 2);
                ldmx4(a[mi][0], a[mi][1], a[mi][2], a[mi][3], addr);
            }
            uint32_t b[4][2];
            #pragma unroll
            for (int nj2 = 0; nj2 < 2; nj2++) {
                uint32_t addr = bB + (uint32_t)(((nrow + nj2 * 16) * LDT + k0 + kaddB) * 2);
                uint32_t r0, r1, r2, r3;
                ldmx4(r0, r1, r2, r3, addr);
                b[nj2 * 2 + 0][0] = r0; b[nj2 * 2 + 0][1] = r1;
                b[nj2 * 2 + 1][0] = r2; b[nj2 * 2 + 1][1] = r3;
            }
            #pragma unroll
            for (int mi = 0; mi < 2; mi++)
                #pragma unroll
                for (int nj = 0; nj < 4; nj++)
                    mma_bf16(d[mi][nj], a[mi], b[nj]);
        }
    }

    // epilogue
    const float* sb = (const float*)(sm + OFF_BIAS);
    int qrow = lane >> 2, qcol = (lane & 3) * 2;
    #pragma unroll
    for (int mi = 0; mi < 2; mi++) {
        #pragma unroll
        for (int half = 0; half < 2; half++) {
            int gm = m0 + wy * 32 + mi * 16 + qrow + half * 8;
            if (gm < M) {
                #pragma unroll
                for (int nj = 0; nj < 4; nj++) {
                    int gc = wx * 32 + nj * 8 + qcol;
                    float x0 = d[mi][nj][half * 2 + 0] + sb[gc];
                    float x1 = d[mi][nj][half * 2 + 1] + sb[gc + 1];
                    if (MODE >= 1) {
                        x0 = (x0 > 0.f) ? x0 : 0.2f * x0;
                        x1 = (x1 > 0.f) ? x1 : 0.2f * x1;
                    }
                    float2* p = (float2*)(C + (size_t)gm * 128 + gc);
                    if (MODE == 2) {
                        float2 c = *p;
                        x0 += c.x;
                        x1 += c.y;
                    }
                    *p = make_float2(x0, x1);
                }
            }
        }
    }
}

// ---------------- K1: row max-norm -------------------------------------------------
__global__ __launch_bounds__(256) void k_normalize(const float* __restrict__ ent,
                                                   const float* __restrict__ rel) {
    int row = blockIdx.x * 8 + (threadIdx.x >> 5);
    int l   = threadIdx.x & 31;
    const float* src;
    float* dst;
    if (row < N_ENTS) {
        src = ent + (size_t)row * EDIM;
        dst = g_EntN + (size_t)row * EDIM;
    } else {
        int r = row - N_ENTS;
        if (r >= N_RELS) return;
        src = rel + (size_t)r * EDIM;
        dst = g_RelN + (size_t)r * EDIM;
    }
    float4 v = ((const float4*)src)[l];
    float ss = v.x * v.x + v.y * v.y + v.z * v.z + v.w * v.w;
    #pragma unroll
    for (int o = 16; o; o >>= 1) ss += __shfl_xor_sync(0xffffffffu, ss, o);
    float n = sqrtf(ss);
    float s = fminf(1.0f, 1.0f / fmaxf(n, 1e-12f));
    ((float4*)dst)[l] = make_float4(v.x * s, v.y * s, v.z * s, v.w * s);
}

// ---------------- K3: attention + aggregation --------------------------------------
__global__ __launch_bounds__(128) void k_main(const int* __restrict__ idx,
                                              const int* __restrict__ adj_ent,
                                              const int* __restrict__ adj_rel) {
    __shared__ __align__(16) float s_hr[128];
    __shared__ __align__(16) float s_h[128];
    __shared__ float s_sc[32];
    __shared__ float s_att[32];
    __shared__ int   s_eid[32];
    __shared__ int   s_rid[32];

    int b   = blockIdx.x;
    int tid = threadIdx.x;

    int ib = idx[b];
    ib = min(max(ib, 0), N_ENTS - 1);

    if (tid < 32) {
        int e = adj_ent[(size_t)ib * KNBR + tid];
        s_eid[tid] = min(max(e, 0), N_ENTS - 1);
        int r = adj_rel[(size_t)ib * KNBR + tid];
        s_rid[tid] = min(max(r, 0), N_RELS - 1);
    }
    s_hr[tid] = g_TrT[(size_t)ib * EDIM + tid];
    s_h[tid]  = g_EntN[(size_t)ib * EDIM + tid];
    __syncthreads();

    int w = tid >> 5, l = tid & 31;
    float4 hr4 = *(const float4*)(s_hr + l * 4);

    #pragma unroll
    for (int kk = 0; kk < 8; kk++) {
        int k = w * 8 + kk;
        int e = s_eid[k], r = s_rid[k];
        float4 tr = *(const float4*)(g_TrT + (size_t)e * EDIM + l * 4);
        float4 rv = *(const float4*)(g_RelN + (size_t)r * EDIM + l * 4);
        float p = tanhf(hr4.x + rv.x) * tr.x + tanhf(hr4.y + rv.y) * tr.y +
                  tanhf(hr4.z + rv.z) * tr.z + tanhf(hr4.w + rv.w) * tr.w;
        #pragma unroll
        for (int o = 16; o; o >>= 1) p += __shfl_xor_sync(0xffffffffu, p, o);
        if (l == 0) s_sc[k] = p;
    }
    __syncthreads();

    if (tid < 32) {
        float sc = s_sc[tid];
        float mx = sc;
        #pragma unroll
        for (int o = 16; o; o >>= 1) mx = fmaxf(mx, __shfl_xor_sync(0xffffffffu, mx, o));
        float ex = __expf(sc - mx);
        float sum = ex;
        #pragma unroll
        for (int o = 16; o; o >>= 1) sum += __shfl_xor_sync(0xffffffffu, sum, o);
        s_att[tid] = ex / sum;
    }
    __syncthreads();

    float acc = 0.f;
    #pragma unroll
    for (int k = 0; k < KNBR; k++)
        acc = fmaf(s_att[k], g_EntN[(size_t)s_eid[k] * EDIM + tid], acc);

    float hv = s_h[tid];
    g_X1[(size_t)b * EDIM + tid] = hv + acc;
    g_X2[(size_t)b * EDIM + tid] = hv * acc;
}

// ---------------- launch ------------------------------------------------------------
extern "C" void kernel_launch(void* const* d_in, const int* in_sizes, int n_in,
                              void* d_out, int out_size) {
    const int*   idx     = (const int*)d_in[0];
    const int*   adj_ent = (const int*)d_in[1];
    const int*   adj_rel = (const int*)d_in[2];
    const float* ent     = (const float*)d_in[3];
    const float* rel     = (const float*)d_in[4];
    const float* Wr_w    = (const float*)d_in[5];
    const float* Wr_b    = (const float*)d_in[6];
    const float* W1_w    = (const float*)d_in[7];
    const float* W1_b    = (const float*)d_in[8];
    const float* W2_w    = (const float*)d_in[9];
    const float* W2_b    = (const float*)d_in[10];
    float* out = (float*)d_out;

    cudaFuncSetAttribute(k_gemm_mma<0>, cudaFuncAttributeMaxDynamicSharedMemorySize, SMEM_MM);
    cudaFuncSetAttribute(k_gemm_mma<1>, cudaFuncAttributeMaxDynamicSharedMemorySize, SMEM_MM);
    cudaFuncSetAttribute(k_gemm_mma<2>, cudaFuncAttributeMaxDynamicSharedMemorySize, SMEM_MM);

    float *EntN, *TrT, *X1, *X2;
    cudaGetSymbolAddress((void**)&EntN, g_EntN);
    cudaGetSymbolAddress((void**)&TrT,  g_TrT);
    cudaGetSymbolAddress((void**)&X1,   g_X1);
    cudaGetSymbolAddress((void**)&X2,   g_X2);

    k_normalize<<<(N_ENTS + N_RELS + 7) / 8, 256>>>(ent, rel);
    k_gemm_mma<0><<<(N_ENTS + 63) / 64, 256, SMEM_MM>>>(EntN, Wr_w, Wr_b, TrT, N_ENTS);
    k_main<<<BATCH, 128>>>(idx, adj_ent, adj_rel);
    k_gemm_mma<1><<<BATCH / 64, 256, SMEM_MM>>>(X1, W1_w, W1_b, out, BATCH);
    k_gemm_mma<2><<<BATCH / 64, 256, SMEM_MM>>>(X2, W2_w, W2_b, out, BATCH);
}